// round 1
// baseline (speedup 1.0000x reference)
#include <cuda_runtime.h>

// GCN layer: out = D^-1/2 A D^-1/2 (X W + b)
// N=100000 nodes, E=1600000 edges, D_IN=256, D_OUT=128
//
// Pipeline (all graph-capturable, default stream, no allocations):
//  1. init:       zero deg / cnt / fill
//  2. deg_count:  per-edge atomicAdd of vals into deg[row], +1 into cnt[row]
//  3. dinv:       d^-1/2 per node
//  4. scan1/2/3:  exclusive prefix sum of cnt -> rowstart (CSR offsets)
//  5. bucket:     scatter edges into CSR order, precompute norm weight per edge
//  6. gemm:       support = X @ W + b   (tiled SIMT fp32)
//  7. spmm:       warp-per-row gather-accumulate (NO feature atomics)

#define N_NODES 100000
#define N_EDGES 1600000
#define D_IN    256
#define D_OUT   128

#define SCAN_BS 1024
#define N_SCAN_BLOCKS ((N_NODES + SCAN_BS - 1) / SCAN_BS)   // 98

// ---- scratch (static device memory; allowed, unlike allocation) ----
__device__ float g_deg[N_NODES];
__device__ float g_dinv[N_NODES];
__device__ int   g_cnt[N_NODES];
__device__ int   g_fill[N_NODES];
__device__ int   g_rowstart[N_NODES + 1];
__device__ int   g_blocksum[N_SCAN_BLOCKS];
__device__ int   g_blockoff[N_SCAN_BLOCKS];
__device__ float g_support[(size_t)N_NODES * D_OUT];   // 51.2 MB
__device__ int   g_ecol[N_EDGES];
__device__ float g_ew[N_EDGES];

// ---------------------------------------------------------------- init
__global__ void k_init() {
    int i = blockIdx.x * blockDim.x + threadIdx.x;
    if (i < N_NODES) {
        g_deg[i]  = 0.0f;
        g_cnt[i]  = 0;
        g_fill[i] = 0;
    }
}

// --------------------------------------------------------- degree count
__global__ void k_deg_count(const int* __restrict__ row,
                            const float* __restrict__ vals) {
    int e = blockIdx.x * blockDim.x + threadIdx.x;
    if (e < N_EDGES) {
        int r = row[e];
        atomicAdd(&g_deg[r], vals[e]);
        atomicAdd(&g_cnt[r], 1);
    }
}

// ------------------------------------------------------------------ dinv
__global__ void k_dinv() {
    int i = blockIdx.x * blockDim.x + threadIdx.x;
    if (i < N_NODES) {
        float d = g_deg[i];
        g_dinv[i] = (d > 0.0f) ? rsqrtf(fmaxf(d, 1e-12f)) : 0.0f;
    }
}

// --------------------------------------------------- scan stage 1 (per block)
__global__ void k_scan1() {
    __shared__ int warp_sums[32];
    int b = blockIdx.x, t = threadIdx.x;
    int i = b * SCAN_BS + t;
    int v = (i < N_NODES) ? g_cnt[i] : 0;

    // warp-inclusive scan
    int x = v;
    #pragma unroll
    for (int o = 1; o < 32; o <<= 1) {
        int y = __shfl_up_sync(0xFFFFFFFFu, x, o);
        if ((t & 31) >= o) x += y;
    }
    if ((t & 31) == 31) warp_sums[t >> 5] = x;
    __syncthreads();
    if (t < 32) {
        int s = warp_sums[t];
        #pragma unroll
        for (int o = 1; o < 32; o <<= 1) {
            int y = __shfl_up_sync(0xFFFFFFFFu, s, o);
            if (t >= o) s += y;
        }
        warp_sums[t] = s;
    }
    __syncthreads();
    int warp_off = (t >= 32) ? warp_sums[(t >> 5) - 1] : 0;
    int excl = x - v + warp_off;
    if (i < N_NODES) g_rowstart[i] = excl;
    if (t == SCAN_BS - 1) g_blocksum[b] = excl + v;  // block total
}

// -------------------------------------------- scan stage 2 (block sums, 1 CTA)
__global__ void k_scan2() {
    __shared__ int tmp[128];
    int t = threadIdx.x;
    int v = (t < N_SCAN_BLOCKS) ? g_blocksum[t] : 0;
    tmp[t] = v;
    __syncthreads();
    for (int o = 1; o < 128; o <<= 1) {
        int y = (t >= o) ? tmp[t - o] : 0;
        __syncthreads();
        tmp[t] += y;
        __syncthreads();
    }
    int incl = tmp[t];
    if (t < N_SCAN_BLOCKS) g_blockoff[t] = incl - v;
    if (t == 127) g_rowstart[N_NODES] = incl;   // == total edge count
}

// ------------------------------------------------- scan stage 3 (add offsets)
__global__ void k_scan3() {
    int i = blockIdx.x * blockDim.x + threadIdx.x;
    if (i < N_NODES) g_rowstart[i] += g_blockoff[i / SCAN_BS];
}

// ---------------------------------------------------------------- bucket
__global__ void k_bucket(const int* __restrict__ row,
                         const int* __restrict__ col,
                         const float* __restrict__ vals) {
    int e = blockIdx.x * blockDim.x + threadIdx.x;
    if (e < N_EDGES) {
        int r = row[e];
        int c = col[e];
        int pos = g_rowstart[r] + atomicAdd(&g_fill[r], 1);
        g_ecol[pos] = c;
        g_ew[pos]   = vals[e] * g_dinv[r] * g_dinv[c];
    }
}

// ------------------------------------------------------------------ GEMM
// support = X[N, 256] @ W[256, 128] + b[128]
// Tile: BM=64 rows x 128 cols, BK=32, 256 threads, 4x8 register tile/thread.
#define BM 64
#define BK 32
__global__ __launch_bounds__(256) void k_gemm(const float* __restrict__ x,
                                              const float* __restrict__ W,
                                              const float* __restrict__ bias) {
    __shared__ float xs[BK][BM + 1];     // [k][m], +1 pad -> conflict-free
    __shared__ float ws[BK][D_OUT];      // [k][n]

    int tid = threadIdx.x;
    int tx = tid & 15;        // 0..15  -> output cols tx + 16*j
    int ty = tid >> 4;        // 0..15  -> output rows ty*4 + i
    int row0 = blockIdx.x * BM;

    float acc[4][8];
    #pragma unroll
    for (int i = 0; i < 4; i++)
        #pragma unroll
        for (int j = 0; j < 8; j++) acc[i][j] = 0.0f;

    for (int k0 = 0; k0 < D_IN; k0 += BK) {
        // load X tile transposed into xs[k][m]  (coalesced gmem, conflict-free smem)
        int lk = tid & 31;
        int lm0 = tid >> 5;   // 0..7
        #pragma unroll
        for (int p = 0; p < 8; p++) {
            int m = lm0 + p * 8;
            int r = row0 + m;
            xs[lk][m] = (r < N_NODES) ? x[(size_t)r * D_IN + k0 + lk] : 0.0f;
        }
        // load W tile into ws[k][n]
        int ln  = tid & 127;
        int lk2 = tid >> 7;   // 0..1
        #pragma unroll
        for (int p = 0; p < 16; p++) {
            int k = lk2 + p * 2;
            ws[k][ln] = W[(size_t)(k0 + k) * D_OUT + ln];
        }
        __syncthreads();

        #pragma unroll
        for (int k = 0; k < BK; k++) {
            float a[4], bb[8];
            #pragma unroll
            for (int i = 0; i < 4; i++) a[i] = xs[k][ty * 4 + i];
            #pragma unroll
            for (int j = 0; j < 8; j++) bb[j] = ws[k][tx + 16 * j];
            #pragma unroll
            for (int i = 0; i < 4; i++)
                #pragma unroll
                for (int j = 0; j < 8; j++) acc[i][j] += a[i] * bb[j];
        }
        __syncthreads();
    }

    #pragma unroll
    for (int i = 0; i < 4; i++) {
        int r = row0 + ty * 4 + i;
        if (r < N_NODES) {
            #pragma unroll
            for (int j = 0; j < 8; j++) {
                int c = tx + 16 * j;
                g_support[(size_t)r * D_OUT + c] = acc[i][j] + bias[c];
            }
        }
    }
}

// ------------------------------------------------------------------ SpMM
// One warp per destination row: gather neighbor support rows (coalesced 512B),
// accumulate in registers (float4 per lane), single coalesced store. No atomics.
__global__ __launch_bounds__(256) void k_spmm(float* __restrict__ out) {
    int w = (blockIdx.x * blockDim.x + threadIdx.x) >> 5;
    int lane = threadIdx.x & 31;
    if (w >= N_NODES) return;

    int e0 = g_rowstart[w];
    int e1 = g_rowstart[w + 1];

    float4 acc = make_float4(0.0f, 0.0f, 0.0f, 0.0f);
    for (int e = e0; e < e1; e++) {
        int   c  = __ldg(&g_ecol[e]);
        float wt = __ldg(&g_ew[e]);
        float4 v = ((const float4*)(g_support + (size_t)c * D_OUT))[lane];
        acc.x += wt * v.x;
        acc.y += wt * v.y;
        acc.z += wt * v.z;
        acc.w += wt * v.w;
    }
    ((float4*)(out + (size_t)w * D_OUT))[lane] = acc;
}

// ------------------------------------------------------------- launcher
extern "C" void kernel_launch(void* const* d_in, const int* in_sizes, int n_in,
                              void* d_out, int out_size) {
    const float* x    = (const float*)d_in[0];
    const int*   row  = (const int*)  d_in[1];
    const int*   col  = (const int*)  d_in[2];
    const float* vals = (const float*)d_in[3];
    const float* W    = (const float*)d_in[4];
    const float* bias = (const float*)d_in[5];
    float* out = (float*)d_out;

    (void)in_sizes; (void)n_in; (void)out_size;

    const int TB = 256;
    k_init     <<<(N_NODES + TB - 1) / TB, TB>>>();
    k_deg_count<<<(N_EDGES + TB - 1) / TB, TB>>>(row, vals);
    k_dinv     <<<(N_NODES + TB - 1) / TB, TB>>>();
    k_scan1    <<<N_SCAN_BLOCKS, SCAN_BS>>>();
    k_scan2    <<<1, 128>>>();
    k_scan3    <<<(N_NODES + TB - 1) / TB, TB>>>();
    k_bucket   <<<(N_EDGES + TB - 1) / TB, TB>>>(row, col, vals);
    k_gemm     <<<(N_NODES + BM - 1) / BM, 256>>>(x, W, bias);
    k_spmm     <<<(N_NODES * 32 + TB - 1) / TB, TB>>>(out);
}

// round 2
// speedup vs baseline: 1.7755x; 1.7755x over previous
#include <cuda_runtime.h>
#include <cstdint>

// GCN layer: out = D^-1/2 A D^-1/2 (X W + b)
// N=100000 nodes, E=1600000 edges, D_IN=256, D_OUT=128
//
// R2: GEMM moved from SIMT FFMA to tf32 mma.sync (m16n8k8) with RNA rounding
//     at smem store; dinv fused into scan1; scan3 folded into bucket/spmm.

#define N_NODES 100000
#define N_EDGES 1600000
#define D_IN    256
#define D_OUT   128

#define SCAN_BS 1024
#define N_SCAN_BLOCKS ((N_NODES + SCAN_BS - 1) / SCAN_BS)   // 98

// ---- scratch (static device memory) ----
__device__ float g_deg[N_NODES];
__device__ float g_dinv[N_NODES];
__device__ int   g_cnt[N_NODES];
__device__ int   g_fill[N_NODES];
__device__ int   g_rowstart[N_NODES + 1];   // per-block exclusive scan (partial)
__device__ int   g_blocksum[N_SCAN_BLOCKS];
__device__ int   g_blockoff[N_SCAN_BLOCKS];
__device__ float g_support[(size_t)N_NODES * D_OUT];   // 51.2 MB
__device__ int   g_ecol[N_EDGES];
__device__ float g_ew[N_EDGES];

// ---------------------------------------------------------------- init
__global__ void k_init() {
    int i = blockIdx.x * blockDim.x + threadIdx.x;
    if (i < N_NODES) {
        g_deg[i]  = 0.0f;
        g_cnt[i]  = 0;
        g_fill[i] = 0;
    }
}

// --------------------------------------------------------- degree count
__global__ void k_deg_count(const int* __restrict__ row,
                            const float* __restrict__ vals) {
    int e = blockIdx.x * blockDim.x + threadIdx.x;
    if (e < N_EDGES) {
        int r = row[e];
        atomicAdd(&g_deg[r], vals[e]);
        atomicAdd(&g_cnt[r], 1);
    }
}

// --------------------- scan stage 1 (per block) + fused d^-1/2 compute
__global__ void k_scan1() {
    __shared__ int warp_sums[32];
    int b = blockIdx.x, t = threadIdx.x;
    int i = b * SCAN_BS + t;
    int v = (i < N_NODES) ? g_cnt[i] : 0;

    // fused dinv (needs g_deg complete, which k_deg_count guarantees)
    if (i < N_NODES) {
        float d = g_deg[i];
        g_dinv[i] = (d > 0.0f) ? rsqrtf(fmaxf(d, 1e-12f)) : 0.0f;
    }

    int x = v;
    #pragma unroll
    for (int o = 1; o < 32; o <<= 1) {
        int y = __shfl_up_sync(0xFFFFFFFFu, x, o);
        if ((t & 31) >= o) x += y;
    }
    if ((t & 31) == 31) warp_sums[t >> 5] = x;
    __syncthreads();
    if (t < 32) {
        int s = warp_sums[t];
        #pragma unroll
        for (int o = 1; o < 32; o <<= 1) {
            int y = __shfl_up_sync(0xFFFFFFFFu, s, o);
            if (t >= o) s += y;
        }
        warp_sums[t] = s;
    }
    __syncthreads();
    int warp_off = (t >= 32) ? warp_sums[(t >> 5) - 1] : 0;
    int excl = x - v + warp_off;
    if (i < N_NODES) g_rowstart[i] = excl;     // partial (within block)
    if (t == SCAN_BS - 1) g_blocksum[b] = excl + v;
}

// -------------------------------------------- scan stage 2 (block sums)
__global__ void k_scan2() {
    __shared__ int tmp[128];
    int t = threadIdx.x;
    int v = (t < N_SCAN_BLOCKS) ? g_blocksum[t] : 0;
    tmp[t] = v;
    __syncthreads();
    for (int o = 1; o < 128; o <<= 1) {
        int y = (t >= o) ? tmp[t - o] : 0;
        __syncthreads();
        tmp[t] += y;
        __syncthreads();
    }
    int incl = tmp[t];
    if (t < N_SCAN_BLOCKS) g_blockoff[t] = incl - v;
    if (t == 127) g_rowstart[N_NODES] = incl;   // absolute total
}

// ---------------------------------------------------------------- bucket
// (scan stage 3 folded in: absolute offset = partial rowstart + blockoff)
__global__ void k_bucket(const int* __restrict__ row,
                         const int* __restrict__ col,
                         const float* __restrict__ vals) {
    int e = blockIdx.x * blockDim.x + threadIdx.x;
    if (e < N_EDGES) {
        int r = row[e];
        int c = col[e];
        int base = g_rowstart[r] + g_blockoff[r >> 10];
        int pos = base + atomicAdd(&g_fill[r], 1);
        g_ecol[pos] = c;
        g_ew[pos]   = vals[e] * g_dinv[r] * g_dinv[c];
    }
}

// ------------------------------------------------------------------ GEMM
// support = X[N,256] @ W[256,128] + b  via tf32 mma.sync m16n8k8.
// CTA: 128x128 tile, 256 threads = 8 warps as 2(M) x 4(N), warp tile 64x32.
#define GBM 128
#define GBK 32
#define AS_STRIDE 36    // (g*36+tc)%32 == (g*4+tc)%32 -> conflict-free frag LDS
#define BS_STRIDE 136   // (tc*136+g)%32 == (tc*8+g)%32 -> conflict-free

__device__ __forceinline__ uint32_t f2tf32(float f) {
    uint32_t r;
    asm("cvt.rna.tf32.f32 %0, %1;" : "=r"(r) : "f"(f));
    return r;
}

__device__ __forceinline__ void mma_tf32(float* c, const uint32_t* a, const uint32_t* b) {
    asm("mma.sync.aligned.m16n8k8.row.col.f32.tf32.tf32.f32 "
        "{%0,%1,%2,%3}, {%4,%5,%6,%7}, {%8,%9}, {%0,%1,%2,%3};"
        : "+f"(c[0]), "+f"(c[1]), "+f"(c[2]), "+f"(c[3])
        : "r"(a[0]), "r"(a[1]), "r"(a[2]), "r"(a[3]), "r"(b[0]), "r"(b[1]));
}

__global__ __launch_bounds__(256) void k_gemm_mma(const float* __restrict__ x,
                                                  const float* __restrict__ W,
                                                  const float* __restrict__ bias) {
    __shared__ uint32_t as[GBM * AS_STRIDE];   // 18.0 KB
    __shared__ uint32_t bs[GBK * BS_STRIDE];   // 17.4 KB

    int tid  = threadIdx.x;
    int wid  = tid >> 5, lane = tid & 31;
    int g    = lane >> 2, tc = lane & 3;
    int wm   = wid >> 2, wn = wid & 3;         // wm 0..1, wn 0..3
    int row0 = blockIdx.x * GBM;

    float acc[4][4][4];
    #pragma unroll
    for (int mi = 0; mi < 4; mi++)
        #pragma unroll
        for (int ni = 0; ni < 4; ni++)
            #pragma unroll
            for (int q = 0; q < 4; q++) acc[mi][ni][q] = 0.0f;

    // gmem load mapping
    int a_r = tid >> 3;          // 0..31 (row within tile, step 32)
    int a_c = (tid & 7) * 4;     // float4 col within BK=32
    int b_r = tid >> 5;          // 0..7  (k row, step 8)
    int b_c = (tid & 31) * 4;    // col 0..124

    for (int k0 = 0; k0 < D_IN; k0 += GBK) {
        #pragma unroll
        for (int p = 0; p < 4; p++) {
            int m = a_r + 32 * p;
            int r = row0 + m;
            float4 v = (r < N_NODES)
                ? *(const float4*)(x + (size_t)r * D_IN + k0 + a_c)
                : make_float4(0.f, 0.f, 0.f, 0.f);
            uint32_t* d = &as[m * AS_STRIDE + a_c];
            d[0] = f2tf32(v.x); d[1] = f2tf32(v.y);
            d[2] = f2tf32(v.z); d[3] = f2tf32(v.w);
        }
        #pragma unroll
        for (int p = 0; p < 4; p++) {
            int k = b_r + 8 * p;
            float4 v = *(const float4*)(W + (size_t)(k0 + k) * D_OUT + b_c);
            uint32_t* d = &bs[k * BS_STRIDE + b_c];
            d[0] = f2tf32(v.x); d[1] = f2tf32(v.y);
            d[2] = f2tf32(v.z); d[3] = f2tf32(v.w);
        }
        __syncthreads();

        #pragma unroll
        for (int k8 = 0; k8 < 4; k8++) {
            uint32_t af[4][4], bf[4][2];
            #pragma unroll
            for (int mi = 0; mi < 4; mi++) {
                const uint32_t* pa = &as[(wm * 64 + mi * 16 + g) * AS_STRIDE + k8 * 8 + tc];
                af[mi][0] = pa[0];
                af[mi][1] = pa[8 * AS_STRIDE];
                af[mi][2] = pa[4];
                af[mi][3] = pa[8 * AS_STRIDE + 4];
            }
            #pragma unroll
            for (int ni = 0; ni < 4; ni++) {
                const uint32_t* pb = &bs[(k8 * 8 + tc) * BS_STRIDE + wn * 32 + ni * 8 + g];
                bf[ni][0] = pb[0];
                bf[ni][1] = pb[4 * BS_STRIDE];
            }
            #pragma unroll
            for (int mi = 0; mi < 4; mi++)
                #pragma unroll
                for (int ni = 0; ni < 4; ni++)
                    mma_tf32(acc[mi][ni], af[mi], bf[ni]);
        }
        __syncthreads();
    }

    // epilogue: + bias, store fp32 support
    #pragma unroll
    for (int ni = 0; ni < 4; ni++) {
        int c = wn * 32 + ni * 8 + 2 * tc;
        float b0 = __ldg(bias + c);
        float b1 = __ldg(bias + c + 1);
        #pragma unroll
        for (int mi = 0; mi < 4; mi++) {
            int r = row0 + wm * 64 + mi * 16 + g;
            if (r < N_NODES) {
                float2 v0 = make_float2(acc[mi][ni][0] + b0, acc[mi][ni][1] + b1);
                *(float2*)(g_support + (size_t)r * D_OUT + c) = v0;
            }
            if (r + 8 < N_NODES) {
                float2 v1 = make_float2(acc[mi][ni][2] + b0, acc[mi][ni][3] + b1);
                *(float2*)(g_support + (size_t)(r + 8) * D_OUT + c) = v1;
            }
        }
    }
}

// ------------------------------------------------------------------ SpMM
// One warp per destination row, register float4 accumulation, no atomics.
__global__ __launch_bounds__(256) void k_spmm(float* __restrict__ out) {
    int w = (blockIdx.x * blockDim.x + threadIdx.x) >> 5;
    int lane = threadIdx.x & 31;
    if (w >= N_NODES) return;

    int e0 = g_rowstart[w] + g_blockoff[w >> 10];
    int e1 = (w + 1 < N_NODES) ? (g_rowstart[w + 1] + g_blockoff[(w + 1) >> 10])
                               : g_rowstart[N_NODES];

    float4 acc = make_float4(0.f, 0.f, 0.f, 0.f);
    #pragma unroll 4
    for (int e = e0; e < e1; e++) {
        int   c  = __ldg(&g_ecol[e]);
        float wt = __ldg(&g_ew[e]);
        float4 v = __ldg(((const float4*)(g_support + (size_t)c * D_OUT)) + lane);
        acc.x += wt * v.x;
        acc.y += wt * v.y;
        acc.z += wt * v.z;
        acc.w += wt * v.w;
    }
    ((float4*)(out + (size_t)w * D_OUT))[lane] = acc;
}

// ------------------------------------------------------------- launcher
extern "C" void kernel_launch(void* const* d_in, const int* in_sizes, int n_in,
                              void* d_out, int out_size) {
    const float* x    = (const float*)d_in[0];
    const int*   row  = (const int*)  d_in[1];
    const int*   col  = (const int*)  d_in[2];
    const float* vals = (const float*)d_in[3];
    const float* W    = (const float*)d_in[4];
    const float* bias = (const float*)d_in[5];
    float* out = (float*)d_out;

    (void)in_sizes; (void)n_in; (void)out_size;

    const int TB = 256;
    k_init     <<<(N_NODES + TB - 1) / TB, TB>>>();
    k_deg_count<<<(N_EDGES + TB - 1) / TB, TB>>>(row, vals);
    k_scan1    <<<N_SCAN_BLOCKS, SCAN_BS>>>();
    k_scan2    <<<1, 128>>>();
    k_bucket   <<<(N_EDGES + TB - 1) / TB, TB>>>(row, col, vals);
    k_gemm_mma <<<(N_NODES + GBM - 1) / GBM, 256>>>(x, W, bias);
    k_spmm     <<<(N_NODES * 32 + TB - 1) / TB, TB>>>(out);
}

// round 3
// speedup vs baseline: 1.9787x; 1.1144x over previous
#include <cuda_runtime.h>
#include <cuda_fp16.h>
#include <cstdint>

// GCN layer: out = D^-1/2 A D^-1/2 (X W + b)
// N=100000 nodes, E=1600000 edges, D_IN=256, D_OUT=128
//
// R3: support stored fp16 (halves SpMM L2 traffic; 25.6MB fully L2-resident),
//     edges packed (col,weight) int2 -> single LDG.64, 1-warp scan2.

#define N_NODES 100000
#define N_EDGES 1600000
#define D_IN    256
#define D_OUT   128

#define SCAN_BS 1024
#define N_SCAN_BLOCKS ((N_NODES + SCAN_BS - 1) / SCAN_BS)   // 98

// ---- scratch (static device memory) ----
__device__ float  g_deg[N_NODES];
__device__ float  g_dinv[N_NODES];
__device__ int    g_cnt[N_NODES];
__device__ int    g_fill[N_NODES];
__device__ int    g_rowstart[N_NODES + 1];   // per-block partial exclusive scan
__device__ int    g_blocksum[N_SCAN_BLOCKS];
__device__ int    g_blockoff[N_SCAN_BLOCKS];
__device__ __half g_support_h[(size_t)N_NODES * D_OUT];  // 25.6 MB (L2-resident)
__device__ int2   g_epack[N_EDGES];                      // {col, weight-as-int}

// ---------------------------------------------------------------- init
__global__ void k_init() {
    int i = blockIdx.x * blockDim.x + threadIdx.x;
    if (i < N_NODES) {
        g_deg[i]  = 0.0f;
        g_cnt[i]  = 0;
        g_fill[i] = 0;
    }
}

// --------------------------------------------------------- degree count
__global__ void k_deg_count(const int* __restrict__ row,
                            const float* __restrict__ vals) {
    int e = blockIdx.x * blockDim.x + threadIdx.x;
    if (e < N_EDGES) {
        int r = row[e];
        atomicAdd(&g_deg[r], vals[e]);
        atomicAdd(&g_cnt[r], 1);
    }
}

// --------------------- scan stage 1 (per block) + fused d^-1/2 compute
__global__ void k_scan1() {
    __shared__ int warp_sums[32];
    int b = blockIdx.x, t = threadIdx.x;
    int i = b * SCAN_BS + t;
    int v = (i < N_NODES) ? g_cnt[i] : 0;

    if (i < N_NODES) {
        float d = g_deg[i];
        g_dinv[i] = (d > 0.0f) ? rsqrtf(fmaxf(d, 1e-12f)) : 0.0f;
    }

    int x = v;
    #pragma unroll
    for (int o = 1; o < 32; o <<= 1) {
        int y = __shfl_up_sync(0xFFFFFFFFu, x, o);
        if ((t & 31) >= o) x += y;
    }
    if ((t & 31) == 31) warp_sums[t >> 5] = x;
    __syncthreads();
    if (t < 32) {
        int s = warp_sums[t];
        #pragma unroll
        for (int o = 1; o < 32; o <<= 1) {
            int y = __shfl_up_sync(0xFFFFFFFFu, s, o);
            if (t >= o) s += y;
        }
        warp_sums[t] = s;
    }
    __syncthreads();
    int warp_off = (t >= 32) ? warp_sums[(t >> 5) - 1] : 0;
    int excl = x - v + warp_off;
    if (i < N_NODES) g_rowstart[i] = excl;
    if (t == SCAN_BS - 1) g_blocksum[b] = excl + v;
}

// ------------------------------- scan stage 2 (block sums, single warp)
__global__ void k_scan2() {
    int t = threadIdx.x;   // 32 threads
    int carry = 0;
    #pragma unroll
    for (int chunk = 0; chunk < (N_SCAN_BLOCKS + 31) / 32; chunk++) {
        int idx = chunk * 32 + t;
        int v = (idx < N_SCAN_BLOCKS) ? g_blocksum[idx] : 0;
        int x = v;
        #pragma unroll
        for (int o = 1; o < 32; o <<= 1) {
            int y = __shfl_up_sync(0xFFFFFFFFu, x, o);
            if (t >= o) x += y;
        }
        int incl = x + carry;
        if (idx < N_SCAN_BLOCKS) g_blockoff[idx] = incl - v;
        carry = __shfl_sync(0xFFFFFFFFu, incl, 31);
    }
    if (t == 0) g_rowstart[N_NODES] = carry;   // absolute total
}

// ---------------------------------------------------------------- bucket
__global__ void k_bucket(const int* __restrict__ row,
                         const int* __restrict__ col,
                         const float* __restrict__ vals) {
    int e = blockIdx.x * blockDim.x + threadIdx.x;
    if (e < N_EDGES) {
        int r = row[e];
        int c = col[e];
        int base = g_rowstart[r] + g_blockoff[r >> 10];
        int pos = base + atomicAdd(&g_fill[r], 1);
        float wv = vals[e] * g_dinv[r] * g_dinv[c];
        g_epack[pos] = make_int2(c, __float_as_int(wv));
    }
}

// ------------------------------------------------------------------ GEMM
// support = X[N,256] @ W[256,128] + b  via tf32 mma.sync m16n8k8.
// CTA: 128x128 tile, 256 threads = 8 warps as 2(M) x 4(N), warp tile 64x32.
#define GBM 128
#define GBK 32
#define AS_STRIDE 36
#define BS_STRIDE 136

__device__ __forceinline__ uint32_t f2tf32(float f) {
    uint32_t r;
    asm("cvt.rna.tf32.f32 %0, %1;" : "=r"(r) : "f"(f));
    return r;
}

__device__ __forceinline__ void mma_tf32(float* c, const uint32_t* a, const uint32_t* b) {
    asm("mma.sync.aligned.m16n8k8.row.col.f32.tf32.tf32.f32 "
        "{%0,%1,%2,%3}, {%4,%5,%6,%7}, {%8,%9}, {%0,%1,%2,%3};"
        : "+f"(c[0]), "+f"(c[1]), "+f"(c[2]), "+f"(c[3])
        : "r"(a[0]), "r"(a[1]), "r"(a[2]), "r"(a[3]), "r"(b[0]), "r"(b[1]));
}

__global__ __launch_bounds__(256) void k_gemm_mma(const float* __restrict__ x,
                                                  const float* __restrict__ W,
                                                  const float* __restrict__ bias) {
    __shared__ uint32_t as[GBM * AS_STRIDE];
    __shared__ uint32_t bs[GBK * BS_STRIDE];

    int tid  = threadIdx.x;
    int wid  = tid >> 5, lane = tid & 31;
    int g    = lane >> 2, tc = lane & 3;
    int wm   = wid >> 2, wn = wid & 3;
    int row0 = blockIdx.x * GBM;

    float acc[4][4][4];
    #pragma unroll
    for (int mi = 0; mi < 4; mi++)
        #pragma unroll
        for (int ni = 0; ni < 4; ni++)
            #pragma unroll
            for (int q = 0; q < 4; q++) acc[mi][ni][q] = 0.0f;

    int a_r = tid >> 3;
    int a_c = (tid & 7) * 4;
    int b_r = tid >> 5;
    int b_c = (tid & 31) * 4;

    for (int k0 = 0; k0 < D_IN; k0 += GBK) {
        #pragma unroll
        for (int p = 0; p < 4; p++) {
            int m = a_r + 32 * p;
            int r = row0 + m;
            float4 v = (r < N_NODES)
                ? *(const float4*)(x + (size_t)r * D_IN + k0 + a_c)
                : make_float4(0.f, 0.f, 0.f, 0.f);
            uint32_t* d = &as[m * AS_STRIDE + a_c];
            d[0] = f2tf32(v.x); d[1] = f2tf32(v.y);
            d[2] = f2tf32(v.z); d[3] = f2tf32(v.w);
        }
        #pragma unroll
        for (int p = 0; p < 4; p++) {
            int k = b_r + 8 * p;
            float4 v = *(const float4*)(W + (size_t)(k0 + k) * D_OUT + b_c);
            uint32_t* d = &bs[k * BS_STRIDE + b_c];
            d[0] = f2tf32(v.x); d[1] = f2tf32(v.y);
            d[2] = f2tf32(v.z); d[3] = f2tf32(v.w);
        }
        __syncthreads();

        #pragma unroll
        for (int k8 = 0; k8 < 4; k8++) {
            uint32_t af[4][4], bf[4][2];
            #pragma unroll
            for (int mi = 0; mi < 4; mi++) {
                const uint32_t* pa = &as[(wm * 64 + mi * 16 + g) * AS_STRIDE + k8 * 8 + tc];
                af[mi][0] = pa[0];
                af[mi][1] = pa[8 * AS_STRIDE];
                af[mi][2] = pa[4];
                af[mi][3] = pa[8 * AS_STRIDE + 4];
            }
            #pragma unroll
            for (int ni = 0; ni < 4; ni++) {
                const uint32_t* pb = &bs[(k8 * 8 + tc) * BS_STRIDE + wn * 32 + ni * 8 + g];
                bf[ni][0] = pb[0];
                bf[ni][1] = pb[4 * BS_STRIDE];
            }
            #pragma unroll
            for (int mi = 0; mi < 4; mi++)
                #pragma unroll
                for (int ni = 0; ni < 4; ni++)
                    mma_tf32(acc[mi][ni], af[mi], bf[ni]);
        }
        __syncthreads();
    }

    // epilogue: + bias, convert fp16, store half2
    #pragma unroll
    for (int ni = 0; ni < 4; ni++) {
        int c = wn * 32 + ni * 8 + 2 * tc;
        float b0 = __ldg(bias + c);
        float b1 = __ldg(bias + c + 1);
        #pragma unroll
        for (int mi = 0; mi < 4; mi++) {
            int r = row0 + wm * 64 + mi * 16 + g;
            if (r < N_NODES) {
                __half2 h = __floats2half2_rn(acc[mi][ni][0] + b0, acc[mi][ni][1] + b1);
                *(__half2*)(g_support_h + (size_t)r * D_OUT + c) = h;
            }
            if (r + 8 < N_NODES) {
                __half2 h = __floats2half2_rn(acc[mi][ni][2] + b0, acc[mi][ni][3] + b1);
                *(__half2*)(g_support_h + (size_t)(r + 8) * D_OUT + c) = h;
            }
        }
    }
}

// ------------------------------------------------------------------ SpMM
// One warp per destination row. Per edge: one LDG.64 of packed (col,w) amortized
// across the warp, one LDG.64 of 4 fp16 features per lane. fp32 accumulate.
__global__ __launch_bounds__(256) void k_spmm(float* __restrict__ out) {
    int w = (blockIdx.x * blockDim.x + threadIdx.x) >> 5;
    int lane = threadIdx.x & 31;
    if (w >= N_NODES) return;

    int e0 = g_rowstart[w] + g_blockoff[w >> 10];
    int e1 = (w + 1 < N_NODES) ? (g_rowstart[w + 1] + g_blockoff[(w + 1) >> 10])
                               : g_rowstart[N_NODES];

    float4 acc = make_float4(0.f, 0.f, 0.f, 0.f);
    #pragma unroll 4
    for (int e = e0; e < e1; e++) {
        int2  p  = __ldg(&g_epack[e]);
        int   c  = p.x;
        float wt = __int_as_float(p.y);
        uint2 u  = __ldg(((const uint2*)(g_support_h + (size_t)c * D_OUT)) + lane);
        float2 f0 = __half22float2(*(const __half2*)&u.x);
        float2 f1 = __half22float2(*(const __half2*)&u.y);
        acc.x += wt * f0.x;
        acc.y += wt * f0.y;
        acc.z += wt * f1.x;
        acc.w += wt * f1.y;
    }
    ((float4*)(out + (size_t)w * D_OUT))[lane] = acc;
}

// ------------------------------------------------------------- launcher
extern "C" void kernel_launch(void* const* d_in, const int* in_sizes, int n_in,
                              void* d_out, int out_size) {
    const float* x    = (const float*)d_in[0];
    const int*   row  = (const int*)  d_in[1];
    const int*   col  = (const int*)  d_in[2];
    const float* vals = (const float*)d_in[3];
    const float* W    = (const float*)d_in[4];
    const float* bias = (const float*)d_in[5];
    float* out = (float*)d_out;

    (void)in_sizes; (void)n_in; (void)out_size;

    const int TB = 256;
    k_init     <<<(N_NODES + TB - 1) / TB, TB>>>();
    k_deg_count<<<(N_EDGES + TB - 1) / TB, TB>>>(row, vals);
    k_scan1    <<<N_SCAN_BLOCKS, SCAN_BS>>>();
    k_scan2    <<<1, 32>>>();
    k_bucket   <<<(N_EDGES + TB - 1) / TB, TB>>>(row, col, vals);
    k_gemm_mma <<<(N_NODES + GBM - 1) / GBM, 256>>>(x, W, bias);
    k_spmm     <<<(N_NODES * 32 + TB - 1) / TB, TB>>>(out);
}